// round 1
// baseline (speedup 1.0000x reference)
#include <cuda_runtime.h>
#include <cuda_bf16.h>

// L1 TV 1D prox (Condat 2013, direct O(W) algorithm), batched over rows.
// Shapes (fixed for this problem): y (8,3,256,512) fp32, lmbd (1,3) fp32.
// lam = softplus(lmbd[c]) per channel. 6144 independent rows of W=512.
//
// Strategy: one thread per row. Stage 64 rows per block into padded shared
// memory with coalesced float4 global loads, run the serial state machine
// in-place in smem (writes never precede reads at the same index), then
// coalesced float4 store-back.

#define TV_W 512
#define TV_STRIDE 513            // +1 pad: row base bank = tid % 32 -> conflict-free
#define ROWS_PER_BLOCK 64
#define TV_H 256
#define TV_C 3

__global__ void __launch_bounds__(ROWS_PER_BLOCK, 1)
tv1d_condat_kernel(const float* __restrict__ y,
                   const float* __restrict__ lmbd,
                   float* __restrict__ out)
{
    extern __shared__ float s[];   // ROWS_PER_BLOCK * TV_STRIDE floats

    const int tid = threadIdx.x;
    const size_t base = (size_t)blockIdx.x * ROWS_PER_BLOCK * TV_W;

    // ---- coalesced staged load (float4) ----
    {
        const float4* g4 = (const float4*)(y + base);
        #pragma unroll 4
        for (int i = tid; i < ROWS_PER_BLOCK * (TV_W / 4); i += ROWS_PER_BLOCK) {
            int r = i >> 7;            // / (W/4=128)
            int q = i & 127;           // % 128
            float4 v = g4[i];
            float* d = s + r * TV_STRIDE + (q << 2);
            d[0] = v.x; d[1] = v.y; d[2] = v.z; d[3] = v.w;
        }
    }
    __syncthreads();

    // ---- per-thread Condat TV1D, in place on its smem row ----
    {
        const int row = blockIdx.x * ROWS_PER_BLOCK + tid;
        const int c = (row / TV_H) % TV_C;
        const float lv  = lmbd[c];
        // softplus, numerically fine for the values here
        const float lam = log1pf(expf(lv));

        float* yr = s + tid * TV_STRIDE;

        int k = 0, k0 = 0, km = 0, kp = 0;
        float vmin = yr[0] - lam;
        float vmax = yr[0] + lam;
        float umin = lam;
        float umax = -lam;

        for (;;) {
            if (k == TV_W - 1) {
                if (umin < 0.0f) {
                    // flush negative segment at vmin
                    for (int i = k0; i <= km; ++i) yr[i] = vmin;
                    k0 = km + 1; k = k0; km = k0;
                    vmin = yr[k0];
                    umin = lam;
                    umax = vmin + lam - vmax;
                } else if (umax > 0.0f) {
                    // flush positive segment at vmax
                    for (int i = k0; i <= kp; ++i) yr[i] = vmax;
                    k0 = kp + 1; k = k0; kp = k0;
                    vmax = yr[k0];
                    umax = -lam;
                    umin = vmax - lam - vmin;
                } else {
                    // terminate
                    float v = vmin + umin / (float)(k - k0 + 1);
                    for (int i = k0; i <= k; ++i) yr[i] = v;
                    break;
                }
            } else {
                float yn = yr[k + 1];
                float umin_t = umin + yn - vmin;
                float umax_t = umax + yn - vmax;

                if (umin_t < -lam) {
                    // negative jump: flush at vmin, restart after km
                    for (int i = k0; i <= km; ++i) yr[i] = vmin;
                    k0 = km + 1; k = k0; km = k0; kp = k0;
                    vmin = yr[k0];
                    vmax = vmin + 2.0f * lam;
                    umin = lam;
                    umax = -lam;
                } else if (umax_t > lam) {
                    // positive jump: flush at vmax, restart after kp
                    for (int i = k0; i <= kp; ++i) yr[i] = vmax;
                    k0 = kp + 1; k = k0; km = k0; kp = k0;
                    vmax = yr[k0];
                    vmin = vmax - 2.0f * lam;
                    umin = lam;
                    umax = -lam;
                } else {
                    // extend current segment
                    k = k + 1;
                    float denom = (float)(k - k0 + 1);
                    if (umin_t >= lam) {
                        vmin += (umin_t - lam) / denom;
                        umin = lam;
                        km = k;
                    } else {
                        umin = umin_t;
                    }
                    if (umax_t <= -lam) {
                        vmax += (umax_t + lam) / denom;
                        umax = -lam;
                        kp = k;
                    } else {
                        umax = umax_t;
                    }
                }
            }
        }
    }
    __syncthreads();

    // ---- coalesced staged store (float4) ----
    {
        float4* o4 = (float4*)(out + base);
        #pragma unroll 4
        for (int i = tid; i < ROWS_PER_BLOCK * (TV_W / 4); i += ROWS_PER_BLOCK) {
            int r = i >> 7;
            int q = i & 127;
            const float* d = s + r * TV_STRIDE + (q << 2);
            o4[i] = make_float4(d[0], d[1], d[2], d[3]);
        }
    }
}

extern "C" void kernel_launch(void* const* d_in, const int* in_sizes, int n_in,
                              void* d_out, int out_size)
{
    const float* y    = (const float*)d_in[0];
    const float* lmbd = (const float*)d_in[1];
    float* out        = (float*)d_out;

    const int n_rows = in_sizes[0] / TV_W;           // 6144
    const int blocks = n_rows / ROWS_PER_BLOCK;      // 96
    const int smem   = ROWS_PER_BLOCK * TV_STRIDE * sizeof(float); // 131328 B

    static bool attr_set = false;
    // cudaFuncSetAttribute is idempotent and not a stream op; safe under capture.
    cudaFuncSetAttribute(tv1d_condat_kernel,
                         cudaFuncAttributeMaxDynamicSharedMemorySize, smem);

    tv1d_condat_kernel<<<blocks, ROWS_PER_BLOCK, smem>>>(y, lmbd, out);
    (void)attr_set; (void)n_in; (void)out_size;
}

// round 6
// speedup vs baseline: 1.1805x; 1.1805x over previous
#include <cuda_runtime.h>
#include <cuda_bf16.h>

// L1 TV 1D prox (Condat 2013), batched. y (8,3,256,512) fp32, lmbd (1,3).
// lam = softplus(lmbd[c]). 6144 independent rows of W=512, one thread/row.
//
// Round 3: divergence-minimized state machine (round-2 design, infra-failed,
// resubmitted with a restructured hot loop):
//  - tight inner extend loop, fully select-based updates (no BSSY on hot path)
//  - jump/boundary handling hoisted to a single outer region
//  - float denom counter fden == (k-k0+1) invariant (no I2F anywhere)
//  - __fdividef everywhere (MUFU.RCP; rel tol is 1e-3, we deliver ~1e-7)
//  - in-place smem flush (writes [k0..j], subsequent reads start at j+1)

#define TV_W 512
#define TV_STRIDE 513            // +1 pad: base bank = tid % 32
#define ROWS_PER_BLOCK 64
#define TV_H 256
#define TV_C 3

__global__ void __launch_bounds__(ROWS_PER_BLOCK, 1)
tv1d_condat_kernel(const float* __restrict__ y,
                   const float* __restrict__ lmbd,
                   float* __restrict__ out)
{
    extern __shared__ float s[];   // ROWS_PER_BLOCK * TV_STRIDE floats

    const int tid = threadIdx.x;
    const size_t base = (size_t)blockIdx.x * ROWS_PER_BLOCK * TV_W;

    // ---- coalesced staged load (float4) ----
    {
        const float4* g4 = (const float4*)(y + base);
        #pragma unroll 4
        for (int i = tid; i < ROWS_PER_BLOCK * (TV_W / 4); i += ROWS_PER_BLOCK) {
            int r = i >> 7;            // / 128
            int q = i & 127;           // % 128
            float4 v = g4[i];
            float* d = s + r * TV_STRIDE + (q << 2);
            d[0] = v.x; d[1] = v.y; d[2] = v.z; d[3] = v.w;
        }
    }
    __syncthreads();

    // ---- per-thread Condat TV1D, in place on its smem row ----
    {
        const int row = blockIdx.x * ROWS_PER_BLOCK + tid;
        const int c = (row >> 8) % TV_C;          // (row / 256) % 3
        const float lam  = log1pf(expf(lmbd[c])); // softplus
        const float lam2 = 2.0f * lam;

        float* yr = s + tid * TV_STRIDE;

        int   k = 0, k0 = 0, km = 0, kp = 0;
        float y0   = yr[0];
        float vmin = y0 - lam;
        float vmax = y0 + lam;
        float umin = lam;
        float umax = -lam;
        float fden = 1.0f;        // invariant: fden == (k - k0 + 1)

        for (;;) {
            // ---- hot inner loop: extend while no jump ----
            bool jumped = false, jn = false;
            while (k < TV_W - 1) {
                float yn     = yr[k + 1];
                float umin_t = umin + yn - vmin;
                float umax_t = umax + yn - vmax;
                jn = umin_t < -lam;
                if (jn || umax_t > lam) { jumped = true; break; }

                ++k;
                fden += 1.0f;
                float dm = __fdividef(umin_t - lam, fden);
                float dx = __fdividef(umax_t + lam, fden);
                bool hm = umin_t >= lam;
                bool hx = umax_t <= -lam;
                vmin = hm ? vmin + dm : vmin;
                umin = hm ? lam       : umin_t;
                km   = hm ? k         : km;
                vmax = hx ? vmax + dx : vmax;
                umax = hx ? -lam      : umax_t;
                kp   = hx ? k         : kp;
            }

            if (jumped) {
                // ---- merged jump: flush + restart ----
                int   j = jn ? km : kp;
                float v = jn ? vmin : vmax;
                #pragma unroll 1
                for (int i = k0; i <= j; ++i) yr[i] = v;
                k0 = j + 1; k = k0; km = k0; kp = k0;
                float yv = yr[min(k0, TV_W - 1)];
                vmin = jn ? yv : yv - lam2;
                vmax = jn ? yv + lam2 : yv;
                umin = lam; umax = -lam;
                fden = 1.0f;
                continue;
            }

            // ---- boundary phase: k == W-1 ----
            if (umin < 0.0f) {
                #pragma unroll 1
                for (int i = k0; i <= km; ++i) yr[i] = vmin;
                k0 = km + 1; k = k0; km = k0;
                float yv = yr[min(k0, TV_W - 1)];
                float ov = vmax;
                vmin = yv; umin = lam;
                umax = yv + lam - ov;
                fden = 1.0f;
            } else if (umax > 0.0f) {
                #pragma unroll 1
                for (int i = k0; i <= kp; ++i) yr[i] = vmax;
                k0 = kp + 1; k = k0; kp = k0;
                float yv = yr[min(k0, TV_W - 1)];
                float ov = vmin;
                vmax = yv; umax = -lam;
                umin = yv - lam - ov;
                fden = 1.0f;
            } else {
                float v = vmin + __fdividef(umin, fden);
                #pragma unroll 1
                for (int i = k0; i <= k; ++i) yr[i] = v;
                break;
            }
        }
    }
    __syncthreads();

    // ---- coalesced staged store (float4) ----
    {
        float4* o4 = (float4*)(out + base);
        #pragma unroll 4
        for (int i = tid; i < ROWS_PER_BLOCK * (TV_W / 4); i += ROWS_PER_BLOCK) {
            int r = i >> 7;
            int q = i & 127;
            const float* d = s + r * TV_STRIDE + (q << 2);
            o4[i] = make_float4(d[0], d[1], d[2], d[3]);
        }
    }
}

extern "C" void kernel_launch(void* const* d_in, const int* in_sizes, int n_in,
                              void* d_out, int out_size)
{
    const float* y    = (const float*)d_in[0];
    const float* lmbd = (const float*)d_in[1];
    float* out        = (float*)d_out;

    const int n_rows = in_sizes[0] / TV_W;           // 6144
    const int blocks = n_rows / ROWS_PER_BLOCK;      // 96
    const int smem   = ROWS_PER_BLOCK * TV_STRIDE * sizeof(float); // 131328 B

    cudaFuncSetAttribute(tv1d_condat_kernel,
                         cudaFuncAttributeMaxDynamicSharedMemorySize, smem);

    tv1d_condat_kernel<<<blocks, ROWS_PER_BLOCK, smem>>>(y, lmbd, out);
    (void)n_in; (void)out_size;
}

// round 7
// speedup vs baseline: 2.7933x; 2.3662x over previous
#include <cuda_runtime.h>
#include <cuda_bf16.h>

// L1 TV 1D prox (Condat 2013), batched. y (8,3,256,512) fp32, lmbd (1,3).
// lam = softplus(lmbd[c]). 6144 independent rows of W=512.
//
// Round 6: GROUP=8 lanes per row (4 rows per warp).
//  - 1536 warps (vs 192): ~2.6 warps/SMSP latency hiding, occ 3%->~16%
//  - divergence only among 4 rows per warp (was 32)
//  - all 8 lanes of a group run the state machine redundantly (uniform
//    branches within group, broadcast LDS); flushes are 8-lane cooperative
//  - prefetch yr[k+2] before the exit branch to hide LDS latency
//  - warp-private staging: no __syncthreads, only __syncwarp

#define TV_W 512
#define TV_STRIDE 513
#define GROUP 8
#define ROWS_PER_WARP 4          // 32 / GROUP
#define WARPS_PER_BLOCK 8
#define ROWS_PER_BLOCK 32        // WARPS_PER_BLOCK * ROWS_PER_WARP
#define TV_C 3

__global__ void __launch_bounds__(WARPS_PER_BLOCK * 32, 1)
tv1d_condat_kernel(const float* __restrict__ y,
                   const float* __restrict__ lmbd,
                   float* __restrict__ out)
{
    extern __shared__ float s[];   // ROWS_PER_BLOCK * TV_STRIDE floats

    const int wid  = threadIdx.x >> 5;
    const int lane = threadIdx.x & 31;
    const int warp_row0 = blockIdx.x * ROWS_PER_BLOCK + wid * ROWS_PER_WARP;
    float* ws = s + wid * ROWS_PER_WARP * TV_STRIDE;

    // ---- warp-cooperative staged load (float4, coalesced) ----
    {
        const float4* g4 = (const float4*)(y + (size_t)warp_row0 * TV_W);
        #pragma unroll
        for (int i = lane; i < ROWS_PER_WARP * (TV_W / 4); i += 32) {
            int r = i >> 7;            // / 128
            int q = i & 127;           // % 128
            float4 v = g4[i];
            float* d = ws + r * TV_STRIDE + (q << 2);
            d[0] = v.x; d[1] = v.y; d[2] = v.z; d[3] = v.w;
        }
    }
    __syncwarp();

    // ---- group-redundant Condat TV1D, in place on the group's smem row ----
    {
        const int sub = lane >> 3;            // row-in-warp (0..3)
        const int ln  = lane & (GROUP - 1);   // lane-in-group (0..7)
        const int row = warp_row0 + sub;
        const int c   = (row >> 8) % TV_C;    // (row / 256) % 3
        const float lam  = log1pf(expf(lmbd[c]));
        const float lam2 = 2.0f * lam;

        float* yr = s + (wid * ROWS_PER_WARP + sub) * TV_STRIDE;

        int   k = 0, k0 = 0, km = 0, kp = 0;
        float y0   = yr[0];
        float vmin = y0 - lam;
        float vmax = y0 + lam;
        float umin = lam;
        float umax = -lam;
        float fden = 1.0f;        // invariant: fden == (k - k0 + 1)

        for (;;) {
            // ---- hot inner loop: extend while no jump ----
            bool jumped = false, jn = false;
            float yn = yr[min(k + 1, TV_W - 1)];
            while (k < TV_W - 1) {
                float umin_t = umin + yn - vmin;
                float umax_t = umax + yn - vmax;
                float yn2 = yr[min(k + 2, TV_W - 1)];   // prefetch next
                jn = umin_t < -lam;
                if (jn || umax_t > lam) { jumped = true; break; }

                ++k;
                fden += 1.0f;
                float dm = __fdividef(umin_t - lam, fden);
                float dx = __fdividef(umax_t + lam, fden);
                bool hm = umin_t >= lam;
                bool hx = umax_t <= -lam;
                vmin = hm ? vmin + dm : vmin;
                umin = hm ? lam       : umin_t;
                km   = hm ? k         : km;
                vmax = hx ? vmax + dx : vmax;
                umax = hx ? -lam      : umax_t;
                kp   = hx ? k         : kp;
                yn = yn2;
            }

            if (jumped) {
                // ---- merged jump: cooperative flush + restart ----
                int   j = jn ? km : kp;
                float v = jn ? vmin : vmax;
                #pragma unroll 1
                for (int i = k0 + ln; i <= j; i += GROUP) yr[i] = v;
                k0 = j + 1; k = k0; km = k0; kp = k0;
                float yv = yr[min(k0, TV_W - 1)];
                vmin = jn ? yv : yv - lam2;
                vmax = jn ? yv + lam2 : yv;
                umin = lam; umax = -lam;
                fden = 1.0f;
                continue;
            }

            // ---- boundary phase: k == W-1 ----
            if (umin < 0.0f) {
                #pragma unroll 1
                for (int i = k0 + ln; i <= km; i += GROUP) yr[i] = vmin;
                k0 = km + 1; k = k0; km = k0;
                float yv = yr[min(k0, TV_W - 1)];
                float ov = vmax;
                vmin = yv; umin = lam;
                umax = yv + lam - ov;
                fden = 1.0f;
            } else if (umax > 0.0f) {
                #pragma unroll 1
                for (int i = k0 + ln; i <= kp; i += GROUP) yr[i] = vmax;
                k0 = kp + 1; k = k0; kp = k0;
                float yv = yr[min(k0, TV_W - 1)];
                float ov = vmin;
                vmax = yv; umax = -lam;
                umin = yv - lam - ov;
                fden = 1.0f;
            } else {
                float v = vmin + __fdividef(umin, fden);
                #pragma unroll 1
                for (int i = k0 + ln; i <= k; i += GROUP) yr[i] = v;
                break;
            }
        }
    }
    __syncwarp();

    // ---- warp-cooperative staged store (float4, coalesced) ----
    {
        float4* o4 = (float4*)(out + (size_t)warp_row0 * TV_W);
        #pragma unroll
        for (int i = lane; i < ROWS_PER_WARP * (TV_W / 4); i += 32) {
            int r = i >> 7;
            int q = i & 127;
            const float* d = ws + r * TV_STRIDE + (q << 2);
            o4[i] = make_float4(d[0], d[1], d[2], d[3]);
        }
    }
}

extern "C" void kernel_launch(void* const* d_in, const int* in_sizes, int n_in,
                              void* d_out, int out_size)
{
    const float* y    = (const float*)d_in[0];
    const float* lmbd = (const float*)d_in[1];
    float* out        = (float*)d_out;

    const int n_rows = in_sizes[0] / TV_W;               // 6144
    const int blocks = n_rows / ROWS_PER_BLOCK;          // 192
    const int smem   = ROWS_PER_BLOCK * TV_STRIDE * sizeof(float); // 65664 B

    cudaFuncSetAttribute(tv1d_condat_kernel,
                         cudaFuncAttributeMaxDynamicSharedMemorySize, smem);

    tv1d_condat_kernel<<<blocks, WARPS_PER_BLOCK * 32, smem>>>(y, lmbd, out);
    (void)n_in; (void)out_size;
}

// round 8
// speedup vs baseline: 2.9173x; 1.0444x over previous
#include <cuda_runtime.h>
#include <cuda_bf16.h>

// L1 TV 1D prox (Condat 2013), batched. y (8,3,256,512) fp32, lmbd (1,3).
// lam = softplus(lmbd[c]). 6144 rows of W=512, ONE THREAD PER ROW.
//
// Round 7: fully branchless state machine with deferred segment writes.
//  - Condat never reads its own output => flushes can be deferred.
//  - Per trip: O(1) straight-line predicated code (selects, no BSSY),
//    lanes stay converged => no divergence serialization.
//  - On jump: write segment value at its START index + set a bit in a
//    per-thread 512-bit mask. Forward-fill pass reconstructs the output.
//  - Restart reads yr[km+1]/yr[kp+1] prefetched at trip start (latency hidden).

#define TV_W 512
#define TV_STRIDE 513            // +1 pad: per-thread row base bank = tid%32
#define THREADS 64
#define MASK_WORDS 16            // 512 bits
#define MASK_STRIDE 17           // +1 pad for bank-conflict-free mask access
#define TV_C 3

__global__ void __launch_bounds__(THREADS, 1)
tv1d_condat_kernel(const float* __restrict__ y,
                   const float* __restrict__ lmbd,
                   float* __restrict__ out)
{
    extern __shared__ float s[];   // THREADS*TV_STRIDE + THREADS*MASK_STRIDE
    float* rows = s;
    unsigned* maskbuf = (unsigned*)(s + THREADS * TV_STRIDE);

    const int tid = threadIdx.x;
    const size_t base = (size_t)blockIdx.x * THREADS * TV_W;

    // ---- coalesced staged load (float4) ----
    {
        const float4* g4 = (const float4*)(y + base);
        #pragma unroll 4
        for (int i = tid; i < THREADS * (TV_W / 4); i += THREADS) {
            int r = i >> 7;            // / 128
            int q = i & 127;           // % 128
            float4 v = g4[i];
            float* d = rows + r * TV_STRIDE + (q << 2);
            d[0] = v.x; d[1] = v.y; d[2] = v.z; d[3] = v.w;
        }
    }
    // init mask
    unsigned* mw = maskbuf + tid * MASK_STRIDE;
    #pragma unroll
    for (int w = 0; w < MASK_WORDS; ++w) mw[w] = 0u;
    __syncthreads();

    // ---- branchless Condat state machine, one thread per row ----
    {
        const int row = blockIdx.x * THREADS + tid;
        const int c   = (row >> 8) % TV_C;            // (row/256)%3
        const float lam  = log1pf(expf(lmbd[c]));     // softplus
        const float nlam = -lam;
        const float lam2 = 2.0f * lam;

        float* yr = rows + tid * TV_STRIDE;

        int   k = 0, k0 = 0, km = 0, kp = 0;
        float y0   = yr[0];
        float vmin = y0 - lam;
        float vmax = y0 + lam;
        float umin = lam;
        float umax = nlam;
        float fden = 1.0f;        // invariant: fden == (k - k0 + 1)
        bool  done = false;

        #pragma unroll 1
        for (int trip = 0; trip < 8192; ++trip) {
            if (!__any_sync(0xFFFFFFFFu, !done)) break;

            // --- prefetch all shared reads (addresses known at trip start) ---
            float yn  = yr[min(k  + 1, TV_W - 1)];
            float rkm = yr[min(km + 1, TV_W - 1)];   // restart read if neg jump
            float rkp = yr[min(kp + 1, TV_W - 1)];   // restart read if pos jump
            int      wk0  = min(k0, TV_W - 1);
            unsigned mold = mw[wk0 >> 5];

            float fden1 = fden + 1.0f;
            float rcp1  = __fdividef(1.0f, fden1);

            float umin_t = umin + yn - vmin;
            float umax_t = umax + yn - vmax;

            // --- case flags (reference branch order preserved) ---
            bool alive = !done;
            bool e    = (k >= TV_W - 1);
            bool neg  = (e ? (umin < 0.0f)  : (umin_t < nlam)) && alive;
            bool posr =  e ? (umax > 0.0f)  : (umax_t > lam);
            bool pos  = !neg && posr && alive;
            bool term = e && !neg && !pos && alive;
            bool ext  = !e && !neg && !pos && alive;
            bool jmp  = neg || pos;

            int   emit_end = neg ? km : kp;
            int   k0n      = jmp ? emit_end + 1 : k0;
            float rr       = neg ? rkm : rkp;     // == yr[min(k0n, W-1)] on jump
            float val      = neg ? vmin : vmax;

            // --- deferred segment emit (unconditional store is safe:
            //     yr[k0] is never read again by the state machine) ---
            yr[wk0] = val;
            mw[wk0 >> 5] = mold | (jmp ? (1u << (wk0 & 31)) : 0u);

            // --- extend-path candidates ---
            int  k1 = k + 1;
            bool hm = ext && (umin_t >= lam);
            bool hx = ext && (umax_t <= nlam);
            float vmin_ext = hm ? vmin + (umin_t - lam) * rcp1 : vmin;
            float umin_ext = hm ? lam  : umin_t;
            float vmax_ext = hx ? vmax + (umax_t + lam) * rcp1 : vmax;
            float umax_ext = hx ? nlam : umax_t;

            // --- compose new state (old values on RHS throughout) ---
            float vmin_o = vmin, vmax_o = vmax;
            bool pe = pos && e, pb = pos && !e;
            bool ne = neg && e, nb = neg && !e;

            int   k_n    = ext ? k1 : (jmp ? k0n : k);
            int   km_n   = ext ? (hm ? k1 : km) : ((neg || pb) ? k0n : km);
            int   kp_n   = ext ? (hx ? k1 : kp) : ((pos || nb) ? k0n : kp);
            float vmin_n = ext ? vmin_ext : (neg ? rr : (pb ? rr - lam2 : vmin_o));
            float vmax_n = ext ? vmax_ext : (pos ? rr : (nb ? rr + lam2 : vmax_o));
            float umin_n = ext ? umin_ext : (pe ? rr - lam - vmin_o : (jmp ? lam  : umin));
            float umax_n = ext ? umax_ext : (ne ? rr + lam - vmax_o : (jmp ? nlam : umax));
            int   k0_n   = jmp ? k0n : k0;
            float fden_n = ext ? fden1 : (jmp ? 1.0f : fden);

            k = k_n; km = km_n; kp = kp_n; k0 = k0_n;
            vmin = vmin_n; vmax = vmax_n; umin = umin_n; umax = umax_n;
            fden = fden_n;
            done = done || term;
        }

        // --- final (terminate) segment: value at start k0 ---
        {
            int wk0 = min(k0, TV_W - 1);
            yr[wk0] = vmin + umin / fden;
            mw[wk0 >> 5] |= 1u << (wk0 & 31);
        }

        // --- forward-fill pass: expand (start,value) marks to full row ---
        {
            float v = 0.0f;
            #pragma unroll 1
            for (int w = 0; w < MASK_WORDS; ++w) {
                unsigned m = mw[w];
                float* p = yr + (w << 5);
                #pragma unroll
                for (int b = 0; b < 32; ++b) {
                    float x = p[b];
                    v = ((m >> b) & 1u) ? x : v;
                    p[b] = v;
                }
            }
        }
    }
    __syncthreads();

    // ---- coalesced staged store (float4) ----
    {
        float4* o4 = (float4*)(out + base);
        #pragma unroll 4
        for (int i = tid; i < THREADS * (TV_W / 4); i += THREADS) {
            int r = i >> 7;
            int q = i & 127;
            const float* d = rows + r * TV_STRIDE + (q << 2);
            o4[i] = make_float4(d[0], d[1], d[2], d[3]);
        }
    }
}

extern "C" void kernel_launch(void* const* d_in, const int* in_sizes, int n_in,
                              void* d_out, int out_size)
{
    const float* y    = (const float*)d_in[0];
    const float* lmbd = (const float*)d_in[1];
    float* out        = (float*)d_out;

    const int n_rows = in_sizes[0] / TV_W;       // 6144
    const int blocks = n_rows / THREADS;         // 96
    const int smem   = (THREADS * TV_STRIDE) * sizeof(float)
                     + (THREADS * MASK_STRIDE) * sizeof(unsigned);  // 135680 B

    cudaFuncSetAttribute(tv1d_condat_kernel,
                         cudaFuncAttributeMaxDynamicSharedMemorySize, smem);

    tv1d_condat_kernel<<<blocks, THREADS, smem>>>(y, lmbd, out);
    (void)n_in; (void)out_size;
}